// round 16
// baseline (speedup 1.0000x reference)
#include <cuda_runtime.h>
#include <cuda_fp16.h>
#include <mma.h>
#include <math.h>
#include <stdint.h>

using namespace nvcuda;

// ---------------- problem constants ----------------
#define T_TOK 4096
#define HIDN  2048
#define NH    16
#define NKV   4
#define HD    128
#define FF    8192
#define BATCH 4
#define SEQ   1024
#define GRP   (NH / NKV)
#define KVW   (NKV * HD)          // 512
#define NQKV  (HIDN + 2 * KVW)    // 3072
#define EPSV  1e-6f
#define SCALE 0.08838834764831845f
#define NEG16 -60000.0f

// ---------------- fp32 scratch ----------------
#define OFF_X2     ((size_t)0)
#define OFF_BIAS   ((size_t)8388608)
#define SCRATCH_FLOATS ((size_t)8392704)
__device__ float g_scratch[SCRATCH_FLOATS];

// ---------------- fp16 scratch ----------------
#define HW_QKV   ((size_t)0)
#define HW_O     ((size_t)6291456)
#define HW_G     ((size_t)10485760)
#define HW_U     ((size_t)27262976)
#define HW_D     ((size_t)44040192)
#define H_H16    ((size_t)60817408)
#define H_QKV16  ((size_t)69206016)
#define H_Q16    ((size_t)81788928)
#define H_K16    ((size_t)90177536)
#define H_P16    ((size_t)92274688)
#define H_ATTN16 ((size_t)159383552)
#define H_G16    ((size_t)167772160)
#define HSCRATCH_HALVES ((size_t)201326592)
__device__ __half g_hscratch[HSCRATCH_HALVES];

// ---------------- cp.async helpers ----------------
__device__ __forceinline__ void cp16(uint32_t dst, const void* src) {
    asm volatile("cp.async.cg.shared.global [%0], [%1], 16;" :: "r"(dst), "l"(src));
}
__device__ __forceinline__ void cp_commit() {
    asm volatile("cp.async.commit_group;");
}
template <int N>
__device__ __forceinline__ void cp_wait() {
    asm volatile("cp.async.wait_group %0;" :: "n"(N));
}

typedef wmma::fragment<wmma::matrix_a, 16, 16, 16, __half, wmma::row_major> AFragH;
typedef wmma::fragment<wmma::matrix_b, 16, 16, 16, __half, wmma::col_major> BFragHC;
typedef wmma::fragment<wmma::matrix_b, 16, 16, 16, __half, wmma::row_major> BFragHR;
typedef wmma::fragment<wmma::accumulator, 16, 16, 16, float> CFragH;

// ============================================================
// casgemm (R9/R10-proven): 128x128 tile, 256 thr, BK=64,
// 3 stages, 2 CTA/SM.  EPI: 0 none, 1 +bias, 2 +res.
// ============================================================
#define BKC 64
#define CPITCH 72
#define CSTAGE (128 * CPITCH)
#define CAS_SMEM_BYTES (3 * 2 * CSTAGE * 2)

template <int EPI, int HOUT>
__global__ void __launch_bounds__(256, 2)
casgemm_tn(const __half* __restrict__ A, int lda,
           const __half* __restrict__ B, int ldb,
           void* __restrict__ Cv, int ldc, int K,
           const float* __restrict__ bias,
           const float* __restrict__ res)
{
    extern __shared__ __half csmem[];
    const uint32_t sm32 = (uint32_t)__cvta_generic_to_shared(csmem);

    const int tid  = threadIdx.x;
    const int wid  = tid >> 5;
    const int lane = tid & 31;
    const int m0 = blockIdx.y * 128;
    const int n0 = blockIdx.x * 128;
    const int wm = wid & 1, wn = wid >> 1;

    CFragH c[4][2];
#pragma unroll
    for (int i = 0; i < 4; i++)
#pragma unroll
        for (int j = 0; j < 2; j++) wmma::fill_fragment(c[i][j], 0.f);

    const int row = tid >> 1;
    const int cb  = (tid & 1) << 5;
    const __half* gA = A + (size_t)(m0 + row) * lda + cb;
    const __half* gB = B + (size_t)(n0 + row) * ldb + cb;
    const uint32_t tA = sm32 + (uint32_t)(row * CPITCH + cb) * 2u;
    const uint32_t tB = tA + (uint32_t)CSTAGE * 2u;

#define CAS_LOAD(slot, k0) do {                                         \
        const uint32_t _o = (uint32_t)(slot) * (2u * CSTAGE * 2u);      \
        _Pragma("unroll")                                               \
        for (int _u = 0; _u < 4; _u++) {                                \
            cp16(tA + _o + _u * 16u, gA + (k0) + _u * 8);               \
            cp16(tB + _o + _u * 16u, gB + (k0) + _u * 8);               \
        }                                                               \
    } while (0)

    const int nt = K / BKC;

    CAS_LOAD(0, 0);      cp_commit();
    CAS_LOAD(1, BKC);    cp_commit();

    for (int t = 0; t < nt; t++) {
        cp_wait<1>();
        __syncthreads();
        if (t + 2 < nt) CAS_LOAD((t + 2) % 3, (t + 2) * BKC);
        cp_commit();

        const __half* sA = csmem + (t % 3) * 2 * CSTAGE;
        const __half* sB = sA + CSTAGE;
#pragma unroll
        for (int ks = 0; ks < BKC; ks += 16) {
            AFragH af[4];
            BFragHC bf[2];
#pragma unroll
            for (int i = 0; i < 4; i++)
                wmma::load_matrix_sync(af[i], sA + (wm * 64 + i * 16) * CPITCH + ks, CPITCH);
#pragma unroll
            for (int j = 0; j < 2; j++)
                wmma::load_matrix_sync(bf[j], sB + (wn * 32 + j * 16) * CPITCH + ks, CPITCH);
#pragma unroll
            for (int i = 0; i < 4; i++)
#pragma unroll
                for (int j = 0; j < 2; j++)
                    wmma::mma_sync(c[i][j], af[i], bf[j], c[i][j]);
        }
    }
    __syncthreads();

    float* stage = reinterpret_cast<float*>(csmem) + wid * 256;
    const int r  = lane >> 1;
    const int cq = (lane & 1) << 3;
#pragma unroll
    for (int i = 0; i < 4; i++) {
#pragma unroll
        for (int j = 0; j < 2; j++) {
            wmma::store_matrix_sync(stage, c[i][j], 16, wmma::mem_row_major);
            __syncwarp();
            const size_t row_g = (size_t)(m0 + wm * 64 + i * 16 + r);
            const size_t col_g = (size_t)(n0 + wn * 32 + j * 16 + cq);
            float4 v0 = *(float4*)&stage[r * 16 + cq];
            float4 v1 = *(float4*)&stage[r * 16 + cq + 4];
            if (EPI == 1) {
                float4 b0 = *(const float4*)&bias[col_g];
                float4 b1 = *(const float4*)&bias[col_g + 4];
                v0.x += b0.x; v0.y += b0.y; v0.z += b0.z; v0.w += b0.w;
                v1.x += b1.x; v1.y += b1.y; v1.z += b1.z; v1.w += b1.w;
            }
            if (EPI == 2) {
                float4 r0 = *(const float4*)&res[row_g * ldc + col_g];
                float4 r1 = *(const float4*)&res[row_g * ldc + col_g + 4];
                v0.x += r0.x; v0.y += r0.y; v0.z += r0.z; v0.w += r0.w;
                v1.x += r1.x; v1.y += r1.y; v1.z += r1.z; v1.w += r1.w;
            }
            if (HOUT) {
                __half* C = (__half*)Cv;
                __half2 h[4];
                h[0] = __floats2half2_rn(v0.x, v0.y);
                h[1] = __floats2half2_rn(v0.z, v0.w);
                h[2] = __floats2half2_rn(v1.x, v1.y);
                h[3] = __floats2half2_rn(v1.z, v1.w);
                *(uint4*)&C[row_g * ldc + col_g] = *(uint4*)h;
            } else {
                float* C = (float*)Cv;
                *(float4*)&C[row_g * ldc + col_g] = v0;
                *(float4*)&C[row_g * ldc + col_g + 4] = v1;
            }
            __syncwarp();
        }
    }
#undef CAS_LOAD
}

// ============================================================
// casgemm_gu: fused gate+up MLP GEMM.
// ml1 (3-stage) computes gate tile -> silu -> smem stash (slot2 region);
// ml2 (2-stage, slots 0-1) computes up tile; epilogue multiplies by
// stashed silu(gate) and writes fp16 C. Eliminates g16 round trip.
// ============================================================
#define GU_GPITCH 136
#define GU_GOFF   (2 * 2 * CSTAGE)      // halves offset of slot2 = 36864

__global__ void __launch_bounds__(256, 2)
casgemm_gu(const __half* __restrict__ A, int lda,
           const __half* __restrict__ Bg, const __half* __restrict__ Bu, int ldb,
           __half* __restrict__ C, int ldc, int K)
{
    extern __shared__ __half csmem[];
    const uint32_t sm32 = (uint32_t)__cvta_generic_to_shared(csmem);

    const int tid  = threadIdx.x;
    const int wid  = tid >> 5;
    const int lane = tid & 31;
    const int m0 = blockIdx.y * 128;
    const int n0 = blockIdx.x * 128;
    const int wm = wid & 1, wn = wid >> 1;

    const int row = tid >> 1;
    const int cb  = (tid & 1) << 5;
    const __half* gA  = A  + (size_t)(m0 + row) * lda + cb;
    const __half* gBg = Bg + (size_t)(n0 + row) * ldb + cb;
    const __half* gBu = Bu + (size_t)(n0 + row) * ldb + cb;
    const uint32_t tA = sm32 + (uint32_t)(row * CPITCH + cb) * 2u;
    const uint32_t tB = tA + (uint32_t)CSTAGE * 2u;

    const int nt = K / BKC;
    float* stage = reinterpret_cast<float*>(csmem) + wid * 256;
    __half* gateS = csmem + GU_GOFF;
    const int r  = lane >> 1;
    const int cq = (lane & 1) << 3;

    CFragH c[4][2];
#pragma unroll
    for (int i = 0; i < 4; i++)
#pragma unroll
        for (int j = 0; j < 2; j++) wmma::fill_fragment(c[i][j], 0.f);

#define GU_LOAD(slot, k0, GB) do {                                      \
        const uint32_t _o = (uint32_t)(slot) * (2u * CSTAGE * 2u);      \
        _Pragma("unroll")                                               \
        for (int _u = 0; _u < 4; _u++) {                                \
            cp16(tA + _o + _u * 16u, gA + (k0) + _u * 8);               \
            cp16(tB + _o + _u * 16u, (GB) + (k0) + _u * 8);             \
        }                                                               \
    } while (0)

    // ---------------- mainloop 1: gate (3-stage) ----------------
    GU_LOAD(0, 0,   gBg);  cp_commit();
    GU_LOAD(1, BKC, gBg);  cp_commit();
    for (int t = 0; t < nt; t++) {
        cp_wait<1>();
        __syncthreads();
        if (t + 2 < nt) GU_LOAD((t + 2) % 3, (t + 2) * BKC, gBg);
        cp_commit();

        const __half* sA = csmem + (t % 3) * 2 * CSTAGE;
        const __half* sB = sA + CSTAGE;
#pragma unroll
        for (int ks = 0; ks < BKC; ks += 16) {
            AFragH af[4];
            BFragHC bf[2];
#pragma unroll
            for (int i = 0; i < 4; i++)
                wmma::load_matrix_sync(af[i], sA + (wm * 64 + i * 16) * CPITCH + ks, CPITCH);
#pragma unroll
            for (int j = 0; j < 2; j++)
                wmma::load_matrix_sync(bf[j], sB + (wn * 32 + j * 16) * CPITCH + ks, CPITCH);
#pragma unroll
            for (int i = 0; i < 4; i++)
#pragma unroll
                for (int j = 0; j < 2; j++)
                    wmma::mma_sync(c[i][j], af[i], bf[j], c[i][j]);
        }
    }
    __syncthreads();

    // stash silu(gate) as fp16 into slot2 region
#pragma unroll
    for (int i = 0; i < 4; i++) {
#pragma unroll
        for (int j = 0; j < 2; j++) {
            wmma::store_matrix_sync(stage, c[i][j], 16, wmma::mem_row_major);
            __syncwarp();
            float4 v0 = *(float4*)&stage[r * 16 + cq];
            float4 v1 = *(float4*)&stage[r * 16 + cq + 4];
            v0.x = v0.x / (1.f + expf(-v0.x));
            v0.y = v0.y / (1.f + expf(-v0.y));
            v0.z = v0.z / (1.f + expf(-v0.z));
            v0.w = v0.w / (1.f + expf(-v0.w));
            v1.x = v1.x / (1.f + expf(-v1.x));
            v1.y = v1.y / (1.f + expf(-v1.y));
            v1.z = v1.z / (1.f + expf(-v1.z));
            v1.w = v1.w / (1.f + expf(-v1.w));
            __half2 h[4];
            h[0] = __floats2half2_rn(v0.x, v0.y);
            h[1] = __floats2half2_rn(v0.z, v0.w);
            h[2] = __floats2half2_rn(v1.x, v1.y);
            h[3] = __floats2half2_rn(v1.z, v1.w);
            *(uint4*)&gateS[(wm * 64 + i * 16 + r) * GU_GPITCH + wn * 32 + j * 16 + cq] = *(uint4*)h;
            __syncwarp();
        }
    }
    __syncthreads();

    // ---------------- mainloop 2: up (2-stage, slots 0-1) ----------------
#pragma unroll
    for (int i = 0; i < 4; i++)
#pragma unroll
        for (int j = 0; j < 2; j++) wmma::fill_fragment(c[i][j], 0.f);

    GU_LOAD(0, 0, gBu);  cp_commit();
    for (int t = 0; t < nt; t++) {
        if (t + 1 < nt) GU_LOAD((t + 1) & 1, (t + 1) * BKC, gBu);
        cp_commit();
        cp_wait<1>();
        __syncthreads();

        const __half* sA = csmem + (t & 1) * 2 * CSTAGE;
        const __half* sB = sA + CSTAGE;
#pragma unroll
        for (int ks = 0; ks < BKC; ks += 16) {
            AFragH af[4];
            BFragHC bf[2];
#pragma unroll
            for (int i = 0; i < 4; i++)
                wmma::load_matrix_sync(af[i], sA + (wm * 64 + i * 16) * CPITCH + ks, CPITCH);
#pragma unroll
            for (int j = 0; j < 2; j++)
                wmma::load_matrix_sync(bf[j], sB + (wn * 32 + j * 16) * CPITCH + ks, CPITCH);
#pragma unroll
            for (int i = 0; i < 4; i++)
#pragma unroll
                for (int j = 0; j < 2; j++)
                    wmma::mma_sync(c[i][j], af[i], bf[j], c[i][j]);
        }
        __syncthreads();
    }

    // epilogue: C = silu(gate) * up
#pragma unroll
    for (int i = 0; i < 4; i++) {
#pragma unroll
        for (int j = 0; j < 2; j++) {
            wmma::store_matrix_sync(stage, c[i][j], 16, wmma::mem_row_major);
            __syncwarp();
            const size_t row_g = (size_t)(m0 + wm * 64 + i * 16 + r);
            const size_t col_g = (size_t)(n0 + wn * 32 + j * 16 + cq);
            float4 v0 = *(float4*)&stage[r * 16 + cq];
            float4 v1 = *(float4*)&stage[r * 16 + cq + 4];
            uint4 gu = *(uint4*)&gateS[(wm * 64 + i * 16 + r) * GU_GPITCH + wn * 32 + j * 16 + cq];
            __half2* gh = (__half2*)&gu;
            float2 g0 = __half22float2(gh[0]);
            float2 g1 = __half22float2(gh[1]);
            float2 g2 = __half22float2(gh[2]);
            float2 g3 = __half22float2(gh[3]);
            v0.x *= g0.x; v0.y *= g0.y; v0.z *= g1.x; v0.w *= g1.y;
            v1.x *= g2.x; v1.y *= g2.y; v1.z *= g3.x; v1.w *= g3.y;
            __half2 h[4];
            h[0] = __floats2half2_rn(v0.x, v0.y);
            h[1] = __floats2half2_rn(v0.z, v0.w);
            h[2] = __floats2half2_rn(v1.x, v1.y);
            h[3] = __floats2half2_rn(v1.z, v1.w);
            *(uint4*)&C[row_g * ldc + col_g] = *(uint4*)h;
            __syncwarp();
        }
    }
#undef GU_LOAD
}

// ============================================================
// PV cp.async (R14-proven, heavy-first)
// ============================================================
#define PV_APITCH 72
#define PV_ASTAGE (128 * PV_APITCH)
#define PV_BPITCH 136
#define PV_BSTAGE (64 * PV_BPITCH)
#define PV_SLOT   (PV_ASTAGE + PV_BSTAGE)
#define PV_SMEM_BYTES (3 * PV_SLOT * 2)

__global__ void __launch_bounds__(256, 2)
hpv_cas(const __half* __restrict__ p, const __half* __restrict__ v, int ldv,
        __half* __restrict__ out)
{
    extern __shared__ __half csmem[];
    const uint32_t sm32 = (uint32_t)__cvta_generic_to_shared(csmem);

    const int z = blockIdx.z;
    const int b = z / NH, h = z % NH, kvh = h / GRP;
    const int m0 = (gridDim.y - 1 - blockIdx.y) * 128;
    const __half* A = p + (size_t)z * SEQ * SEQ;
    const __half* B = v + (size_t)b * SEQ * ldv + (size_t)kvh * HD;
    __half* C = out + (size_t)b * SEQ * HIDN + (size_t)h * HD;

    const int tid  = threadIdx.x;
    const int wid  = tid >> 5;
    const int lane = tid & 31;
    const int wm = wid & 1, wn = wid >> 1;

    CFragH c[4][2];
#pragma unroll
    for (int i = 0; i < 4; i++)
#pragma unroll
        for (int j = 0; j < 2; j++) wmma::fill_fragment(c[i][j], 0.f);

    const int arow = tid >> 1;
    const int acb  = (tid & 1) << 5;
    const int brow = tid >> 2;
    const int bcb  = (tid & 3) << 5;
    const __half* gA = A + (size_t)(m0 + arow) * SEQ + acb;
    const uint32_t tA = sm32 + (uint32_t)(arow * PV_APITCH + acb) * 2u;
    const uint32_t tB = sm32 + (uint32_t)(PV_ASTAGE + brow * PV_BPITCH + bcb) * 2u;

#define PV_LOAD(slot, k0) do {                                          \
        const uint32_t _o = (uint32_t)(slot) * (PV_SLOT * 2u);          \
        const __half* _gb = B + (size_t)((k0) + brow) * ldv + bcb;      \
        _Pragma("unroll")                                               \
        for (int _u = 0; _u < 4; _u++) {                                \
            cp16(tA + _o + _u * 16u, gA + (k0) + _u * 8);               \
            cp16(tB + _o + _u * 16u, _gb + _u * 8);                     \
        }                                                               \
    } while (0)

    const int nt = (m0 + 128) / BKC;

    PV_LOAD(0, 0);    cp_commit();
    PV_LOAD(1, BKC);  cp_commit();

    for (int t = 0; t < nt; t++) {
        cp_wait<1>();
        __syncthreads();
        if (t + 2 < nt) PV_LOAD((t + 2) % 3, (t + 2) * BKC);
        cp_commit();

        const __half* sA = csmem + (t % 3) * PV_SLOT;
        const __half* sB = sA + PV_ASTAGE;
#pragma unroll
        for (int ks = 0; ks < BKC; ks += 16) {
            AFragH af[4];
            BFragHR bf[2];
#pragma unroll
            for (int i = 0; i < 4; i++)
                wmma::load_matrix_sync(af[i], sA + (wm * 64 + i * 16) * PV_APITCH + ks, PV_APITCH);
#pragma unroll
            for (int j = 0; j < 2; j++)
                wmma::load_matrix_sync(bf[j], sB + ks * PV_BPITCH + (wn * 32 + j * 16), PV_BPITCH);
#pragma unroll
            for (int i = 0; i < 4; i++)
#pragma unroll
                for (int j = 0; j < 2; j++)
                    wmma::mma_sync(c[i][j], af[i], bf[j], c[i][j]);
        }
    }
    __syncthreads();

    float* stage = reinterpret_cast<float*>(csmem) + wid * 256;
    const int r  = lane >> 1;
    const int cq = (lane & 1) << 3;
#pragma unroll
    for (int i = 0; i < 4; i++) {
#pragma unroll
        for (int j = 0; j < 2; j++) {
            wmma::store_matrix_sync(stage, c[i][j], 16, wmma::mem_row_major);
            __syncwarp();
            const size_t row_g = (size_t)(m0 + wm * 64 + i * 16 + r);
            const size_t col_g = (size_t)(wn * 32 + j * 16 + cq);
            float4 v0 = *(float4*)&stage[r * 16 + cq];
            float4 v1 = *(float4*)&stage[r * 16 + cq + 4];
            __half2 hh[4];
            hh[0] = __floats2half2_rn(v0.x, v0.y);
            hh[1] = __floats2half2_rn(v0.z, v0.w);
            hh[2] = __floats2half2_rn(v1.x, v1.y);
            hh[3] = __floats2half2_rn(v1.z, v1.w);
            *(uint4*)&C[row_g * HIDN + col_g] = *(uint4*)hh;
            __syncwarp();
        }
    }
#undef PV_LOAD
}

// ============================================================
// Scores with GQA K-reuse (R15-proven)
// ============================================================
#define SC_BPITCH 136
#define SC_BSZ (128 * SC_BPITCH)
#define SC_APITCH 40
#define SC_ASZ (128 * SC_APITCH)

__global__ void __launch_bounds__(256, 2)
hscores_g4(const __half* __restrict__ q, const __half* __restrict__ k,
           __half* __restrict__ scores)
{
    if (blockIdx.x > blockIdx.y) return;

    const int z = blockIdx.z;
    const int b = z / NKV, kvh = z % NKV;
    const int m0 = blockIdx.y * 128;
    const int n0 = blockIdx.x * 128;
    const bool diag = (blockIdx.x == blockIdx.y);

    __shared__ __align__(16) __half smem[2 * SC_ASZ + SC_BSZ];
    __half* sA[2] = { smem, smem + SC_ASZ };
    __half* sB = smem + 2 * SC_ASZ;

    const int tid  = threadIdx.x;
    const int wid  = tid >> 5;
    const int lane = tid & 31;
    const int wm = wid & 1, wn = wid >> 1;

    {
        const int row = tid >> 1;
        const int ch  = (tid & 1) << 6;
        const __half* gB = k + (size_t)b * SEQ * KVW + (size_t)(n0 + row) * KVW
                             + (size_t)kvh * HD + ch;
        __half* d = sB + row * SC_BPITCH + ch;
#pragma unroll
        for (int u = 0; u < 8; u++)
            *(uint4*)(d + u * 8) = *(const uint4*)(gB + u * 8);
    }

    const int row = tid >> 1;
    const int c0  = (tid & 1) << 4;

#pragma unroll
    for (int g = 0; g < GRP; g++) {
        const int h = kvh * GRP + g;
        const __half* A = q + (size_t)b * SEQ * HIDN + (size_t)h * HD;
        __half* C = scores + (size_t)(((size_t)b * NH + h) * SEQ * SEQ);
        const __half* gA = A + (size_t)(m0 + row) * HIDN + c0;

        CFragH c[4][2];
#pragma unroll
        for (int i = 0; i < 4; i++)
#pragma unroll
            for (int jj = 0; jj < 2; jj++) wmma::fill_fragment(c[i][jj], 0.f);

        uint4 ra0 = *(const uint4*)(gA);
        uint4 ra1 = *(const uint4*)(gA + 8);
        {
            __half* a = sA[0] + row * SC_APITCH + c0;
            *(uint4*)a = ra0; *(uint4*)(a + 8) = ra1;
        }
        __syncthreads();

        const int nt = HD / 32;
        for (int t = 0; t < nt; t++) {
            const int cur = t & 1;
            if (t + 1 < nt) {
                const int k0 = (t + 1) * 32;
                ra0 = *(const uint4*)(gA + k0);
                ra1 = *(const uint4*)(gA + k0 + 8);
            }
#pragma unroll
            for (int ks = 0; ks < 32; ks += 16) {
                AFragH af[4];
                BFragHC bf[2];
#pragma unroll
                for (int i = 0; i < 4; i++)
                    wmma::load_matrix_sync(af[i], sA[cur] + (wm * 64 + i * 16) * SC_APITCH + ks, SC_APITCH);
#pragma unroll
                for (int jj = 0; jj < 2; jj++)
                    wmma::load_matrix_sync(bf[jj], sB + (wn * 32 + jj * 16) * SC_BPITCH + t * 32 + ks, SC_BPITCH);
#pragma unroll
                for (int i = 0; i < 4; i++)
#pragma unroll
                    for (int jj = 0; jj < 2; jj++)
                        wmma::mma_sync(c[i][jj], af[i], bf[jj], c[i][jj]);
            }
            if (t + 1 < nt) {
                const int nxt = cur ^ 1;
                __half* a = sA[nxt] + row * SC_APITCH + c0;
                *(uint4*)a = ra0; *(uint4*)(a + 8) = ra1;
            }
            __syncthreads();
        }

        float* stage = reinterpret_cast<float*>(smem) + wid * 256;
        const int r  = lane >> 1;
        const int cq = (lane & 1) << 3;
#pragma unroll
        for (int i = 0; i < 4; i++) {
#pragma unroll
            for (int jj = 0; jj < 2; jj++) {
                wmma::store_matrix_sync(stage, c[i][jj], 16, wmma::mem_row_major);
                __syncwarp();
                const size_t row_g = (size_t)(m0 + wm * 64 + i * 16 + r);
                const size_t col_g = (size_t)(n0 + wn * 32 + jj * 16 + cq);
                float4 v0 = *(float4*)&stage[r * 16 + cq];
                float4 v1 = *(float4*)&stage[r * 16 + cq + 4];
                if (diag) {
                    if (col_g + 0 > row_g) v0.x = NEG16;
                    if (col_g + 1 > row_g) v0.y = NEG16;
                    if (col_g + 2 > row_g) v0.z = NEG16;
                    if (col_g + 3 > row_g) v0.w = NEG16;
                    if (col_g + 4 > row_g) v1.x = NEG16;
                    if (col_g + 5 > row_g) v1.y = NEG16;
                    if (col_g + 6 > row_g) v1.z = NEG16;
                    if (col_g + 7 > row_g) v1.w = NEG16;
                }
                __half2 hh[4];
                hh[0] = __floats2half2_rn(v0.x, v0.y);
                hh[1] = __floats2half2_rn(v0.z, v0.w);
                hh[2] = __floats2half2_rn(v1.x, v1.y);
                hh[3] = __floats2half2_rn(v1.z, v1.w);
                *(uint4*)&C[row_g * SEQ + col_g] = *(uint4*)hh;
                __syncwarp();
            }
        }
        __syncthreads();
    }
}

// ---------------- elementwise / reduction kernels ----------------

__global__ void __launch_bounds__(256)
f2h_kernel(const float* __restrict__ in, __half* __restrict__ out, int n)
{
    int i = (blockIdx.x * blockDim.x + threadIdx.x) * 8;
    int stride = gridDim.x * blockDim.x * 8;
    for (; i < n; i += stride) {
        float4 v0 = *(const float4*)(in + i);
        float4 v1 = *(const float4*)(in + i + 4);
        __half2 h[4];
        h[0] = __floats2half2_rn(v0.x, v0.y);
        h[1] = __floats2half2_rn(v0.z, v0.w);
        h[2] = __floats2half2_rn(v1.x, v1.y);
        h[3] = __floats2half2_rn(v1.z, v1.w);
        *(uint4*)(out + i) = *(uint4*)h;
    }
}

__global__ void __launch_bounds__(256)
bias_concat_kernel(const float* __restrict__ bq, const float* __restrict__ bk,
                   const float* __restrict__ bv, float* __restrict__ dst)
{
    int i = blockIdx.x * blockDim.x + threadIdx.x;
    if (i < HIDN) dst[i] = bq[i];
    else if (i < HIDN + KVW) dst[i] = bk[i - HIDN];
    else if (i < NQKV) dst[i] = bv[i - HIDN - KVW];
}

// warp-per-row softmax (R15-proven)
__global__ void __launch_bounds__(256)
softmax_kernel(__half* __restrict__ s)
{
    const int rowg = blockIdx.x * 8 + (threadIdx.x >> 5);
    const int lane = threadIdx.x & 31;
    const size_t base = (size_t)rowg * SEQ;
    const int r = rowg & (SEQ - 1);
    const int L = ((r >> 7) + 1) << 7;
    const int np = (L + 255) >> 8;

    float f[32];
    float mx = -1e30f;
    for (int p = 0; p < np; p++) {
        const int idx = p * 256 + lane * 8;
        if (idx < L) {
            uint4 u = *(uint4*)&s[base + idx];
            __half2* hp = (__half2*)&u;
#pragma unroll
            for (int j = 0; j < 4; j++) {
                float2 pv = __half22float2(hp[j]);
                f[p * 8 + j * 2]     = pv.x;
                f[p * 8 + j * 2 + 1] = pv.y;
                mx = fmaxf(mx, fmaxf(pv.x, pv.y));
            }
        }
    }
#pragma unroll
    for (int o = 16; o > 0; o >>= 1) mx = fmaxf(mx, __shfl_xor_sync(0xffffffffu, mx, o));

    float sum = 0.f;
    for (int p = 0; p < np; p++) {
        const int idx = p * 256 + lane * 8;
        if (idx < L) {
#pragma unroll
            for (int j = 0; j < 8; j++) {
                f[p * 8 + j] = expf(f[p * 8 + j] - mx);
                sum += f[p * 8 + j];
            }
        }
    }
#pragma unroll
    for (int o = 16; o > 0; o >>= 1) sum += __shfl_xor_sync(0xffffffffu, sum, o);
    const float inv = 1.f / sum;

    for (int p = 0; p < np; p++) {
        const int idx = p * 256 + lane * 8;
        if (idx < L) {
            __half2 h[4];
#pragma unroll
            for (int j = 0; j < 4; j++)
                h[j] = __floats2half2_rn(f[p * 8 + j * 2] * inv, f[p * 8 + j * 2 + 1] * inv);
            *(uint4*)&s[base + idx] = *(uint4*)h;
        }
    }
}

__global__ void __launch_bounds__(256)
rmsnorm_h_kernel(const float* __restrict__ x, const float* __restrict__ w,
                 __half* __restrict__ out)
{
    const size_t base = (size_t)blockIdx.x * HIDN;
    const int tid = threadIdx.x;
    __shared__ float red[8];

    float v[8];
    float ss = 0.f;
#pragma unroll
    for (int jj = 0; jj < 8; jj++) {
        v[jj] = x[base + tid + jj * 256];
        ss += v[jj] * v[jj];
    }
#pragma unroll
    for (int o = 16; o > 0; o >>= 1) ss += __shfl_xor_sync(0xffffffffu, ss, o);
    if ((tid & 31) == 0) red[tid >> 5] = ss;
    __syncthreads();
    float tot = red[0] + red[1] + red[2] + red[3] + red[4] + red[5] + red[6] + red[7];
    float r = rsqrtf(tot * (1.f / HIDN) + EPSV);
#pragma unroll
    for (int jj = 0; jj < 8; jj++)
        out[base + tid + jj * 256] = __float2half_rn(v[jj] * r * w[tid + jj * 256]);
}

__global__ void __launch_bounds__(128)
head_rms_rope_h_kernel(const __half* __restrict__ buf, int instride, int inoff,
                       const float* __restrict__ w,
                       const float* __restrict__ cs, const float* __restrict__ sn,
                       __half* __restrict__ out16, int outstride, float outscale)
{
    const int t = blockIdx.x;
    const int h = blockIdx.y;
    const int i = threadIdx.x;
    const size_t iidx = (size_t)t * instride + inoff + h * HD + i;
    const size_t oidx = (size_t)t * outstride + h * HD + i;

    float v = __half2float(buf[iidx]);
    float ss = v * v;
#pragma unroll
    for (int o = 16; o > 0; o >>= 1) ss += __shfl_xor_sync(0xffffffffu, ss, o);
    __shared__ float red[4];
    if ((i & 31) == 0) red[i >> 5] = ss;
    __syncthreads();
    float tot = red[0] + red[1] + red[2] + red[3];
    float n = v * rsqrtf(tot * (1.f / HD) + EPSV) * w[i];

    __shared__ float sm[HD];
    sm[i] = n;
    __syncthreads();
    float rot = (i < 64) ? -sm[i + 64] : sm[i - 64];
    float r = (n * cs[(size_t)t * HD + i] + rot * sn[(size_t)t * HD + i]) * outscale;
    out16[oidx] = __float2half_rn(r);
}

extern "C" void kernel_launch(void* const* d_in, const int* in_sizes, int n_in,
                              void* d_out, int out_size)
{
    const float* x    = (const float*)d_in[0];
    const float* cosv = (const float*)d_in[1];
    const float* sinv = (const float*)d_in[2];
    const float* wq   = (const float*)d_in[4];
    const float* bq   = (const float*)d_in[5];
    const float* wk   = (const float*)d_in[6];
    const float* bk   = (const float*)d_in[7];
    const float* wv   = (const float*)d_in[8];
    const float* bv   = (const float*)d_in[9];
    const float* wo   = (const float*)d_in[10];
    const float* qw   = (const float*)d_in[11];
    const float* kw   = (const float*)d_in[12];
    const float* ln1  = (const float*)d_in[13];
    const float* ln2  = (const float*)d_in[14];
    const float* wg   = (const float*)d_in[15];
    const float* wu   = (const float*)d_in[16];
    const float* wd   = (const float*)d_in[17];
    float* out = (float*)d_out;

    float* s = nullptr;
    cudaGetSymbolAddress((void**)&s, g_scratch);
    __half* hs = nullptr;
    cudaGetSymbolAddress((void**)&hs, g_hscratch);

    float* x2     = s + OFF_X2;
    float* biasc  = s + OFF_BIAS;

    __half* hwqkv  = hs + HW_QKV;
    __half* hwo    = hs + HW_O;
    __half* hwg    = hs + HW_G;
    __half* hwu    = hs + HW_U;
    __half* hwd    = hs + HW_D;
    __half* h16    = hs + H_H16;
    __half* qkv16  = hs + H_QKV16;
    __half* q16    = hs + H_Q16;
    __half* k16    = hs + H_K16;
    __half* p16    = hs + H_P16;
    __half* at16   = hs + H_ATTN16;
    __half* g16    = hs + H_G16;

    cudaFuncSetAttribute(casgemm_tn<1, 1>, cudaFuncAttributeMaxDynamicSharedMemorySize, CAS_SMEM_BYTES);
    cudaFuncSetAttribute(casgemm_tn<2, 0>, cudaFuncAttributeMaxDynamicSharedMemorySize, CAS_SMEM_BYTES);
    cudaFuncSetAttribute(casgemm_gu,       cudaFuncAttributeMaxDynamicSharedMemorySize, CAS_SMEM_BYTES);
    cudaFuncSetAttribute(hpv_cas,          cudaFuncAttributeMaxDynamicSharedMemorySize, PV_SMEM_BYTES);

    // 0. weights fp32 -> fp16
    f2h_kernel<<<2048, 256>>>(wq, hwqkv,                       HIDN * HIDN);
    f2h_kernel<<<512,  256>>>(wk, hwqkv + HIDN * HIDN,         KVW * HIDN);
    f2h_kernel<<<512,  256>>>(wv, hwqkv + (HIDN + KVW) * HIDN, KVW * HIDN);
    f2h_kernel<<<2048, 256>>>(wo, hwo, HIDN * HIDN);
    f2h_kernel<<<4096, 256>>>(wg, hwg, FF * HIDN);
    f2h_kernel<<<4096, 256>>>(wu, hwu, FF * HIDN);
    f2h_kernel<<<4096, 256>>>(wd, hwd, HIDN * FF);
    bias_concat_kernel<<<12, 256>>>(bq, bk, bv, biasc);

    // 1. h16 = rmsnorm(x, ln1)
    rmsnorm_h_kernel<<<T_TOK, 256>>>(x, ln1, h16);

    // 2. fused QKV projection (+bias) -> fp16 qkv16
    casgemm_tn<1, 1><<<dim3(NQKV / 128, T_TOK / 128), 256, CAS_SMEM_BYTES>>>(
        h16, HIDN, hwqkv, HIDN, qkv16, NQKV, HIDN, biasc, nullptr);

    // 3-4. per-head RMS + RoPE -> q16 (pre-scaled) / k16 ; V stays in qkv16
    head_rms_rope_h_kernel<<<dim3(T_TOK, NH),  HD>>>(qkv16, NQKV, 0,    qw, cosv, sinv, q16, HIDN, SCALE);
    head_rms_rope_h_kernel<<<dim3(T_TOK, NKV), HD>>>(qkv16, NQKV, HIDN, kw, cosv, sinv, k16, KVW, 1.0f);

    // 5. scores -> fp16 p16 (GQA K-reuse, lower triangle, analytic mask)
    hscores_g4<<<dim3(SEQ / 128, SEQ / 128, BATCH * NKV), 256>>>(q16, k16, p16);

    // 6. softmax in place (warp-per-row)
    softmax_kernel<<<BATCH * NH * SEQ / 8, 256>>>(p16);

    // 7. attn16 = P @ V (cp.async, heavy-first; V in-place in qkv16)
    hpv_cas<<<dim3(1, SEQ / 128, BATCH * NH), 256, PV_SMEM_BYTES>>>(
        p16, qkv16 + HIDN + KVW, NQKV, at16);

    // 8. x2 = x + attn @ wo^T
    casgemm_tn<2, 0><<<dim3(HIDN / 128, T_TOK / 128), 256, CAS_SMEM_BYTES>>>(
        at16, HIDN, hwo, HIDN, x2, HIDN, HIDN, nullptr, x);

    // 9. h16 = rmsnorm(x2, ln2)
    rmsnorm_h_kernel<<<T_TOK, 256>>>(x2, ln2, h16);

    // 10. fused gate+up: g16 = silu(h16 @ wg^T) * (h16 @ wu^T)
    casgemm_gu<<<dim3(FF / 128, T_TOK / 128), 256, CAS_SMEM_BYTES>>>(
        h16, HIDN, hwg, hwu, HIDN, g16, FF, HIDN);

    // 11. out = x2 + g16 @ wd^T
    casgemm_tn<2, 0><<<dim3(HIDN / 128, T_TOK / 128), 256, CAS_SMEM_BYTES>>>(
        g16, FF, hwd, FF, out, HIDN, FF, nullptr, x2);
}

// round 17
// speedup vs baseline: 1.0150x; 1.0150x over previous
#include <cuda_runtime.h>
#include <cuda_fp16.h>
#include <mma.h>
#include <math.h>
#include <stdint.h>

using namespace nvcuda;

// ---------------- problem constants ----------------
#define T_TOK 4096
#define HIDN  2048
#define NH    16
#define NKV   4
#define HD    128
#define FF    8192
#define BATCH 4
#define SEQ   1024
#define GRP   (NH / NKV)
#define KVW   (NKV * HD)          // 512
#define NQKV  (HIDN + 2 * KVW)    // 3072
#define EPSV  1e-6f
#define SCALE 0.08838834764831845f
#define NEG16 -60000.0f

// ---------------- fp32 scratch ----------------
#define OFF_X2     ((size_t)0)
#define OFF_BIAS   ((size_t)8388608)
#define SCRATCH_FLOATS ((size_t)8392704)
__device__ float g_scratch[SCRATCH_FLOATS];

// ---------------- fp16 scratch ----------------
#define HW_QKV   ((size_t)0)
#define HW_O     ((size_t)6291456)
#define HW_G     ((size_t)10485760)
#define HW_U     ((size_t)27262976)
#define HW_D     ((size_t)44040192)
#define H_H16    ((size_t)60817408)
#define H_QKV16  ((size_t)69206016)
#define H_Q16    ((size_t)81788928)
#define H_K16    ((size_t)90177536)
#define H_P16    ((size_t)92274688)
#define H_ATTN16 ((size_t)159383552)
#define H_G16    ((size_t)167772160)
#define HSCRATCH_HALVES ((size_t)201326592)
__device__ __half g_hscratch[HSCRATCH_HALVES];

// weight segment boundaries (floats), destinations contiguous in g_hscratch
#define SEG_WQ_END ((int)4194304)
#define SEG_WK_END ((int)5242880)
#define SEG_WV_END ((int)6291456)
#define SEG_WO_END ((int)10485760)
#define SEG_WG_END ((int)27262976)
#define SEG_WU_END ((int)44040192)
#define SEG_WD_END ((int)60817408)

// ---------------- cp.async helpers ----------------
__device__ __forceinline__ void cp16(uint32_t dst, const void* src) {
    asm volatile("cp.async.cg.shared.global [%0], [%1], 16;" :: "r"(dst), "l"(src));
}
__device__ __forceinline__ void cp_commit() {
    asm volatile("cp.async.commit_group;");
}
template <int N>
__device__ __forceinline__ void cp_wait() {
    asm volatile("cp.async.wait_group %0;" :: "n"(N));
}

typedef wmma::fragment<wmma::matrix_a, 16, 16, 16, __half, wmma::row_major> AFragH;
typedef wmma::fragment<wmma::matrix_b, 16, 16, 16, __half, wmma::col_major> BFragHC;
typedef wmma::fragment<wmma::matrix_b, 16, 16, 16, __half, wmma::row_major> BFragHR;
typedef wmma::fragment<wmma::accumulator, 16, 16, 16, float> CFragH;

// ============================================================
// casgemm (R9/R10-proven): 128x128 tile, 256 thr, BK=64,
// 3 stages, 2 CTA/SM.  EPI: 0 none, 1 +bias, 2 +res, 3 silu.
// ============================================================
#define BKC 64
#define CPITCH 72
#define CSTAGE (128 * CPITCH)
#define CAS_SMEM_BYTES (3 * 2 * CSTAGE * 2)

template <int EPI, int HOUT>
__global__ void __launch_bounds__(256, 2)
casgemm_tn(const __half* __restrict__ A, int lda,
           const __half* __restrict__ B, int ldb,
           void* __restrict__ Cv, int ldc, int K,
           const float* __restrict__ bias,
           const float* __restrict__ res,
           const __half* __restrict__ resH)
{
    extern __shared__ __half csmem[];
    const uint32_t sm32 = (uint32_t)__cvta_generic_to_shared(csmem);

    const int tid  = threadIdx.x;
    const int wid  = tid >> 5;
    const int lane = tid & 31;
    const int m0 = blockIdx.y * 128;
    const int n0 = blockIdx.x * 128;
    const int wm = wid & 1, wn = wid >> 1;

    CFragH c[4][2];
#pragma unroll
    for (int i = 0; i < 4; i++)
#pragma unroll
        for (int j = 0; j < 2; j++) wmma::fill_fragment(c[i][j], 0.f);

    const int row = tid >> 1;
    const int cb  = (tid & 1) << 5;
    const __half* gA = A + (size_t)(m0 + row) * lda + cb;
    const __half* gB = B + (size_t)(n0 + row) * ldb + cb;
    const uint32_t tA = sm32 + (uint32_t)(row * CPITCH + cb) * 2u;
    const uint32_t tB = tA + (uint32_t)CSTAGE * 2u;

#define CAS_LOAD(slot, k0) do {                                         \
        const uint32_t _o = (uint32_t)(slot) * (2u * CSTAGE * 2u);      \
        _Pragma("unroll")                                               \
        for (int _u = 0; _u < 4; _u++) {                                \
            cp16(tA + _o + _u * 16u, gA + (k0) + _u * 8);               \
            cp16(tB + _o + _u * 16u, gB + (k0) + _u * 8);               \
        }                                                               \
    } while (0)

    const int nt = K / BKC;

    CAS_LOAD(0, 0);      cp_commit();
    CAS_LOAD(1, BKC);    cp_commit();

    for (int t = 0; t < nt; t++) {
        cp_wait<1>();
        __syncthreads();
        if (t + 2 < nt) CAS_LOAD((t + 2) % 3, (t + 2) * BKC);
        cp_commit();

        const __half* sA = csmem + (t % 3) * 2 * CSTAGE;
        const __half* sB = sA + CSTAGE;
#pragma unroll
        for (int ks = 0; ks < BKC; ks += 16) {
            AFragH af[4];
            BFragHC bf[2];
#pragma unroll
            for (int i = 0; i < 4; i++)
                wmma::load_matrix_sync(af[i], sA + (wm * 64 + i * 16) * CPITCH + ks, CPITCH);
#pragma unroll
            for (int j = 0; j < 2; j++)
                wmma::load_matrix_sync(bf[j], sB + (wn * 32 + j * 16) * CPITCH + ks, CPITCH);
#pragma unroll
            for (int i = 0; i < 4; i++)
#pragma unroll
                for (int j = 0; j < 2; j++)
                    wmma::mma_sync(c[i][j], af[i], bf[j], c[i][j]);
        }
    }
    __syncthreads();

    float* stage = reinterpret_cast<float*>(csmem) + wid * 256;
    const int r  = lane >> 1;
    const int cq = (lane & 1) << 3;
#pragma unroll
    for (int i = 0; i < 4; i++) {
#pragma unroll
        for (int j = 0; j < 2; j++) {
            wmma::store_matrix_sync(stage, c[i][j], 16, wmma::mem_row_major);
            __syncwarp();
            const size_t row_g = (size_t)(m0 + wm * 64 + i * 16 + r);
            const size_t col_g = (size_t)(n0 + wn * 32 + j * 16 + cq);
            float4 v0 = *(float4*)&stage[r * 16 + cq];
            float4 v1 = *(float4*)&stage[r * 16 + cq + 4];
            if (EPI == 1) {
                float4 b0 = *(const float4*)&bias[col_g];
                float4 b1 = *(const float4*)&bias[col_g + 4];
                v0.x += b0.x; v0.y += b0.y; v0.z += b0.z; v0.w += b0.w;
                v1.x += b1.x; v1.y += b1.y; v1.z += b1.z; v1.w += b1.w;
            }
            if (EPI == 2) {
                float4 r0 = *(const float4*)&res[row_g * ldc + col_g];
                float4 r1 = *(const float4*)&res[row_g * ldc + col_g + 4];
                v0.x += r0.x; v0.y += r0.y; v0.z += r0.z; v0.w += r0.w;
                v1.x += r1.x; v1.y += r1.y; v1.z += r1.z; v1.w += r1.w;
            }
            if (EPI == 3) {
                uint4 gu = *(const uint4*)&resH[row_g * ldc + col_g];
                __half2* gh = (__half2*)&gu;
                float2 g0 = __half22float2(gh[0]);
                float2 g1 = __half22float2(gh[1]);
                float2 g2 = __half22float2(gh[2]);
                float2 g3 = __half22float2(gh[3]);
                v0.x *= g0.x / (1.f + expf(-g0.x));
                v0.y *= g0.y / (1.f + expf(-g0.y));
                v0.z *= g1.x / (1.f + expf(-g1.x));
                v0.w *= g1.y / (1.f + expf(-g1.y));
                v1.x *= g2.x / (1.f + expf(-g2.x));
                v1.y *= g2.y / (1.f + expf(-g2.y));
                v1.z *= g3.x / (1.f + expf(-g3.x));
                v1.w *= g3.y / (1.f + expf(-g3.y));
            }
            if (HOUT) {
                __half* C = (__half*)Cv;
                __half2 h[4];
                h[0] = __floats2half2_rn(v0.x, v0.y);
                h[1] = __floats2half2_rn(v0.z, v0.w);
                h[2] = __floats2half2_rn(v1.x, v1.y);
                h[3] = __floats2half2_rn(v1.z, v1.w);
                *(uint4*)&C[row_g * ldc + col_g] = *(uint4*)h;
            } else {
                float* C = (float*)Cv;
                *(float4*)&C[row_g * ldc + col_g] = v0;
                *(float4*)&C[row_g * ldc + col_g + 4] = v1;
            }
            __syncwarp();
        }
    }
#undef CAS_LOAD
}

// ============================================================
// PV cp.async (R14-proven, heavy-first)
// ============================================================
#define PV_APITCH 72
#define PV_ASTAGE (128 * PV_APITCH)
#define PV_BPITCH 136
#define PV_BSTAGE (64 * PV_BPITCH)
#define PV_SLOT   (PV_ASTAGE + PV_BSTAGE)
#define PV_SMEM_BYTES (3 * PV_SLOT * 2)

__global__ void __launch_bounds__(256, 2)
hpv_cas(const __half* __restrict__ p, const __half* __restrict__ v, int ldv,
        __half* __restrict__ out)
{
    extern __shared__ __half csmem[];
    const uint32_t sm32 = (uint32_t)__cvta_generic_to_shared(csmem);

    const int z = blockIdx.z;
    const int b = z / NH, h = z % NH, kvh = h / GRP;
    const int m0 = (gridDim.y - 1 - blockIdx.y) * 128;
    const __half* A = p + (size_t)z * SEQ * SEQ;
    const __half* B = v + (size_t)b * SEQ * ldv + (size_t)kvh * HD;
    __half* C = out + (size_t)b * SEQ * HIDN + (size_t)h * HD;

    const int tid  = threadIdx.x;
    const int wid  = tid >> 5;
    const int lane = tid & 31;
    const int wm = wid & 1, wn = wid >> 1;

    CFragH c[4][2];
#pragma unroll
    for (int i = 0; i < 4; i++)
#pragma unroll
        for (int j = 0; j < 2; j++) wmma::fill_fragment(c[i][j], 0.f);

    const int arow = tid >> 1;
    const int acb  = (tid & 1) << 5;
    const int brow = tid >> 2;
    const int bcb  = (tid & 3) << 5;
    const __half* gA = A + (size_t)(m0 + arow) * SEQ + acb;
    const uint32_t tA = sm32 + (uint32_t)(arow * PV_APITCH + acb) * 2u;
    const uint32_t tB = sm32 + (uint32_t)(PV_ASTAGE + brow * PV_BPITCH + bcb) * 2u;

#define PV_LOAD(slot, k0) do {                                          \
        const uint32_t _o = (uint32_t)(slot) * (PV_SLOT * 2u);          \
        const __half* _gb = B + (size_t)((k0) + brow) * ldv + bcb;      \
        _Pragma("unroll")                                               \
        for (int _u = 0; _u < 4; _u++) {                                \
            cp16(tA + _o + _u * 16u, gA + (k0) + _u * 8);               \
            cp16(tB + _o + _u * 16u, _gb + _u * 8);                     \
        }                                                               \
    } while (0)

    const int nt = (m0 + 128) / BKC;

    PV_LOAD(0, 0);    cp_commit();
    PV_LOAD(1, BKC);  cp_commit();

    for (int t = 0; t < nt; t++) {
        cp_wait<1>();
        __syncthreads();
        if (t + 2 < nt) PV_LOAD((t + 2) % 3, (t + 2) * BKC);
        cp_commit();

        const __half* sA = csmem + (t % 3) * PV_SLOT;
        const __half* sB = sA + PV_ASTAGE;
#pragma unroll
        for (int ks = 0; ks < BKC; ks += 16) {
            AFragH af[4];
            BFragHR bf[2];
#pragma unroll
            for (int i = 0; i < 4; i++)
                wmma::load_matrix_sync(af[i], sA + (wm * 64 + i * 16) * PV_APITCH + ks, PV_APITCH);
#pragma unroll
            for (int j = 0; j < 2; j++)
                wmma::load_matrix_sync(bf[j], sB + ks * PV_BPITCH + (wn * 32 + j * 16), PV_BPITCH);
#pragma unroll
            for (int i = 0; i < 4; i++)
#pragma unroll
                for (int j = 0; j < 2; j++)
                    wmma::mma_sync(c[i][j], af[i], bf[j], c[i][j]);
        }
    }
    __syncthreads();

    float* stage = reinterpret_cast<float*>(csmem) + wid * 256;
    const int r  = lane >> 1;
    const int cq = (lane & 1) << 3;
#pragma unroll
    for (int i = 0; i < 4; i++) {
#pragma unroll
        for (int j = 0; j < 2; j++) {
            wmma::store_matrix_sync(stage, c[i][j], 16, wmma::mem_row_major);
            __syncwarp();
            const size_t row_g = (size_t)(m0 + wm * 64 + i * 16 + r);
            const size_t col_g = (size_t)(wn * 32 + j * 16 + cq);
            float4 v0 = *(float4*)&stage[r * 16 + cq];
            float4 v1 = *(float4*)&stage[r * 16 + cq + 4];
            __half2 hh[4];
            hh[0] = __floats2half2_rn(v0.x, v0.y);
            hh[1] = __floats2half2_rn(v0.z, v0.w);
            hh[2] = __floats2half2_rn(v1.x, v1.y);
            hh[3] = __floats2half2_rn(v1.z, v1.w);
            *(uint4*)&C[row_g * HIDN + col_g] = *(uint4*)hh;
            __syncwarp();
        }
    }
#undef PV_LOAD
}

// ============================================================
// Scores with GQA K-reuse (R15-proven)
// ============================================================
#define SC_BPITCH 136
#define SC_BSZ (128 * SC_BPITCH)
#define SC_APITCH 40
#define SC_ASZ (128 * SC_APITCH)

__global__ void __launch_bounds__(256, 2)
hscores_g4(const __half* __restrict__ q, const __half* __restrict__ k,
           __half* __restrict__ scores)
{
    if (blockIdx.x > blockIdx.y) return;

    const int z = blockIdx.z;
    const int b = z / NKV, kvh = z % NKV;
    const int m0 = blockIdx.y * 128;
    const int n0 = blockIdx.x * 128;
    const bool diag = (blockIdx.x == blockIdx.y);

    __shared__ __align__(16) __half smem[2 * SC_ASZ + SC_BSZ];
    __half* sA[2] = { smem, smem + SC_ASZ };
    __half* sB = smem + 2 * SC_ASZ;

    const int tid  = threadIdx.x;
    const int wid  = tid >> 5;
    const int lane = tid & 31;
    const int wm = wid & 1, wn = wid >> 1;

    {
        const int row = tid >> 1;
        const int ch  = (tid & 1) << 6;
        const __half* gB = k + (size_t)b * SEQ * KVW + (size_t)(n0 + row) * KVW
                             + (size_t)kvh * HD + ch;
        __half* d = sB + row * SC_BPITCH + ch;
#pragma unroll
        for (int u = 0; u < 8; u++)
            *(uint4*)(d + u * 8) = *(const uint4*)(gB + u * 8);
    }

    const int row = tid >> 1;
    const int c0  = (tid & 1) << 4;

#pragma unroll
    for (int g = 0; g < GRP; g++) {
        const int h = kvh * GRP + g;
        const __half* A = q + (size_t)b * SEQ * HIDN + (size_t)h * HD;
        __half* C = scores + (size_t)(((size_t)b * NH + h) * SEQ * SEQ);
        const __half* gA = A + (size_t)(m0 + row) * HIDN + c0;

        CFragH c[4][2];
#pragma unroll
        for (int i = 0; i < 4; i++)
#pragma unroll
            for (int jj = 0; jj < 2; jj++) wmma::fill_fragment(c[i][jj], 0.f);

        uint4 ra0 = *(const uint4*)(gA);
        uint4 ra1 = *(const uint4*)(gA + 8);
        {
            __half* a = sA[0] + row * SC_APITCH + c0;
            *(uint4*)a = ra0; *(uint4*)(a + 8) = ra1;
        }
        __syncthreads();

        const int nt = HD / 32;
        for (int t = 0; t < nt; t++) {
            const int cur = t & 1;
            if (t + 1 < nt) {
                const int k0 = (t + 1) * 32;
                ra0 = *(const uint4*)(gA + k0);
                ra1 = *(const uint4*)(gA + k0 + 8);
            }
#pragma unroll
            for (int ks = 0; ks < 32; ks += 16) {
                AFragH af[4];
                BFragHC bf[2];
#pragma unroll
                for (int i = 0; i < 4; i++)
                    wmma::load_matrix_sync(af[i], sA[cur] + (wm * 64 + i * 16) * SC_APITCH + ks, SC_APITCH);
#pragma unroll
                for (int jj = 0; jj < 2; jj++)
                    wmma::load_matrix_sync(bf[jj], sB + (wn * 32 + jj * 16) * SC_BPITCH + t * 32 + ks, SC_BPITCH);
#pragma unroll
                for (int i = 0; i < 4; i++)
#pragma unroll
                    for (int jj = 0; jj < 2; jj++)
                        wmma::mma_sync(c[i][jj], af[i], bf[jj], c[i][jj]);
            }
            if (t + 1 < nt) {
                const int nxt = cur ^ 1;
                __half* a = sA[nxt] + row * SC_APITCH + c0;
                *(uint4*)a = ra0; *(uint4*)(a + 8) = ra1;
            }
            __syncthreads();
        }

        float* stage = reinterpret_cast<float*>(smem) + wid * 256;
        const int r  = lane >> 1;
        const int cq = (lane & 1) << 3;
#pragma unroll
        for (int i = 0; i < 4; i++) {
#pragma unroll
            for (int jj = 0; jj < 2; jj++) {
                wmma::store_matrix_sync(stage, c[i][jj], 16, wmma::mem_row_major);
                __syncwarp();
                const size_t row_g = (size_t)(m0 + wm * 64 + i * 16 + r);
                const size_t col_g = (size_t)(n0 + wn * 32 + jj * 16 + cq);
                float4 v0 = *(float4*)&stage[r * 16 + cq];
                float4 v1 = *(float4*)&stage[r * 16 + cq + 4];
                if (diag) {
                    if (col_g + 0 > row_g) v0.x = NEG16;
                    if (col_g + 1 > row_g) v0.y = NEG16;
                    if (col_g + 2 > row_g) v0.z = NEG16;
                    if (col_g + 3 > row_g) v0.w = NEG16;
                    if (col_g + 4 > row_g) v1.x = NEG16;
                    if (col_g + 5 > row_g) v1.y = NEG16;
                    if (col_g + 6 > row_g) v1.z = NEG16;
                    if (col_g + 7 > row_g) v1.w = NEG16;
                }
                __half2 hh[4];
                hh[0] = __floats2half2_rn(v0.x, v0.y);
                hh[1] = __floats2half2_rn(v0.z, v0.w);
                hh[2] = __floats2half2_rn(v1.x, v1.y);
                hh[3] = __floats2half2_rn(v1.z, v1.w);
                *(uint4*)&C[row_g * SEQ + col_g] = *(uint4*)hh;
                __syncwarp();
            }
        }
        __syncthreads();
    }
}

// ---------------- elementwise / reduction kernels ----------------

// single-launch weight conversion: dst index == global index (contiguous
// destinations in g_hscratch); source picked by segment compare.
__global__ void __launch_bounds__(256)
f2h_all(const float* __restrict__ wq, const float* __restrict__ wk,
        const float* __restrict__ wv, const float* __restrict__ wo,
        const float* __restrict__ wg, const float* __restrict__ wu,
        const float* __restrict__ wd, __half* __restrict__ out)
{
    int i = (blockIdx.x * blockDim.x + threadIdx.x) * 8;
    const int stride = gridDim.x * blockDim.x * 8;
    for (; i < SEG_WD_END; i += stride) {
        const float* src;
        if      (i < SEG_WQ_END) src = wq + i;
        else if (i < SEG_WK_END) src = wk + (i - SEG_WQ_END);
        else if (i < SEG_WV_END) src = wv + (i - SEG_WK_END);
        else if (i < SEG_WO_END) src = wo + (i - SEG_WV_END);
        else if (i < SEG_WG_END) src = wg + (i - SEG_WO_END);
        else if (i < SEG_WU_END) src = wu + (i - SEG_WG_END);
        else                     src = wd + (i - SEG_WU_END);
        float4 v0 = *(const float4*)(src);
        float4 v1 = *(const float4*)(src + 4);
        __half2 h[4];
        h[0] = __floats2half2_rn(v0.x, v0.y);
        h[1] = __floats2half2_rn(v0.z, v0.w);
        h[2] = __floats2half2_rn(v1.x, v1.y);
        h[3] = __floats2half2_rn(v1.z, v1.w);
        *(uint4*)(out + i) = *(uint4*)h;
    }
}

__global__ void __launch_bounds__(256)
bias_concat_kernel(const float* __restrict__ bq, const float* __restrict__ bk,
                   const float* __restrict__ bv, float* __restrict__ dst)
{
    int i = blockIdx.x * blockDim.x + threadIdx.x;
    if (i < HIDN) dst[i] = bq[i];
    else if (i < HIDN + KVW) dst[i] = bk[i - HIDN];
    else if (i < NQKV) dst[i] = bv[i - HIDN - KVW];
}

// warp-per-row softmax (R15-proven)
__global__ void __launch_bounds__(256)
softmax_kernel(__half* __restrict__ s)
{
    const int rowg = blockIdx.x * 8 + (threadIdx.x >> 5);
    const int lane = threadIdx.x & 31;
    const size_t base = (size_t)rowg * SEQ;
    const int r = rowg & (SEQ - 1);
    const int L = ((r >> 7) + 1) << 7;
    const int np = (L + 255) >> 8;

    float f[32];
    float mx = -1e30f;
    for (int p = 0; p < np; p++) {
        const int idx = p * 256 + lane * 8;
        if (idx < L) {
            uint4 u = *(uint4*)&s[base + idx];
            __half2* hp = (__half2*)&u;
#pragma unroll
            for (int j = 0; j < 4; j++) {
                float2 pv = __half22float2(hp[j]);
                f[p * 8 + j * 2]     = pv.x;
                f[p * 8 + j * 2 + 1] = pv.y;
                mx = fmaxf(mx, fmaxf(pv.x, pv.y));
            }
        }
    }
#pragma unroll
    for (int o = 16; o > 0; o >>= 1) mx = fmaxf(mx, __shfl_xor_sync(0xffffffffu, mx, o));

    float sum = 0.f;
    for (int p = 0; p < np; p++) {
        const int idx = p * 256 + lane * 8;
        if (idx < L) {
#pragma unroll
            for (int j = 0; j < 8; j++) {
                f[p * 8 + j] = expf(f[p * 8 + j] - mx);
                sum += f[p * 8 + j];
            }
        }
    }
#pragma unroll
    for (int o = 16; o > 0; o >>= 1) sum += __shfl_xor_sync(0xffffffffu, sum, o);
    const float inv = 1.f / sum;

    for (int p = 0; p < np; p++) {
        const int idx = p * 256 + lane * 8;
        if (idx < L) {
            __half2 h[4];
#pragma unroll
            for (int j = 0; j < 4; j++)
                h[j] = __floats2half2_rn(f[p * 8 + j * 2] * inv, f[p * 8 + j * 2 + 1] * inv);
            *(uint4*)&s[base + idx] = *(uint4*)h;
        }
    }
}

__global__ void __launch_bounds__(256)
rmsnorm_h_kernel(const float* __restrict__ x, const float* __restrict__ w,
                 __half* __restrict__ out)
{
    const size_t base = (size_t)blockIdx.x * HIDN;
    const int tid = threadIdx.x;
    __shared__ float red[8];

    float v[8];
    float ss = 0.f;
#pragma unroll
    for (int jj = 0; jj < 8; jj++) {
        v[jj] = x[base + tid + jj * 256];
        ss += v[jj] * v[jj];
    }
#pragma unroll
    for (int o = 16; o > 0; o >>= 1) ss += __shfl_xor_sync(0xffffffffu, ss, o);
    if ((tid & 31) == 0) red[tid >> 5] = ss;
    __syncthreads();
    float tot = red[0] + red[1] + red[2] + red[3] + red[4] + red[5] + red[6] + red[7];
    float r = rsqrtf(tot * (1.f / HIDN) + EPSV);
#pragma unroll
    for (int jj = 0; jj < 8; jj++)
        out[base + tid + jj * 256] = __float2half_rn(v[jj] * r * w[tid + jj * 256]);
}

__global__ void __launch_bounds__(128)
head_rms_rope_h_kernel(const __half* __restrict__ buf, int instride, int inoff,
                       const float* __restrict__ w,
                       const float* __restrict__ cs, const float* __restrict__ sn,
                       __half* __restrict__ out16, int outstride, float outscale)
{
    const int t = blockIdx.x;
    const int h = blockIdx.y;
    const int i = threadIdx.x;
    const size_t iidx = (size_t)t * instride + inoff + h * HD + i;
    const size_t oidx = (size_t)t * outstride + h * HD + i;

    float v = __half2float(buf[iidx]);
    float ss = v * v;
#pragma unroll
    for (int o = 16; o > 0; o >>= 1) ss += __shfl_xor_sync(0xffffffffu, ss, o);
    __shared__ float red[4];
    if ((i & 31) == 0) red[i >> 5] = ss;
    __syncthreads();
    float tot = red[0] + red[1] + red[2] + red[3];
    float n = v * rsqrtf(tot * (1.f / HD) + EPSV) * w[i];

    __shared__ float sm[HD];
    sm[i] = n;
    __syncthreads();
    float rot = (i < 64) ? -sm[i + 64] : sm[i - 64];
    float r = (n * cs[(size_t)t * HD + i] + rot * sn[(size_t)t * HD + i]) * outscale;
    out16[oidx] = __float2half_rn(r);
}

extern "C" void kernel_launch(void* const* d_in, const int* in_sizes, int n_in,
                              void* d_out, int out_size)
{
    const float* x    = (const float*)d_in[0];
    const float* cosv = (const float*)d_in[1];
    const float* sinv = (const float*)d_in[2];
    const float* wq   = (const float*)d_in[4];
    const float* bq   = (const float*)d_in[5];
    const float* wk   = (const float*)d_in[6];
    const float* bk   = (const float*)d_in[7];
    const float* wv   = (const float*)d_in[8];
    const float* bv   = (const float*)d_in[9];
    const float* wo   = (const float*)d_in[10];
    const float* qw   = (const float*)d_in[11];
    const float* kw   = (const float*)d_in[12];
    const float* ln1  = (const float*)d_in[13];
    const float* ln2  = (const float*)d_in[14];
    const float* wg   = (const float*)d_in[15];
    const float* wu   = (const float*)d_in[16];
    const float* wd   = (const float*)d_in[17];
    float* out = (float*)d_out;

    float* s = nullptr;
    cudaGetSymbolAddress((void**)&s, g_scratch);
    __half* hs = nullptr;
    cudaGetSymbolAddress((void**)&hs, g_hscratch);

    float* x2     = s + OFF_X2;
    float* biasc  = s + OFF_BIAS;

    __half* hwqkv  = hs + HW_QKV;
    __half* hwo    = hs + HW_O;
    __half* hwg    = hs + HW_G;
    __half* hwu    = hs + HW_U;
    __half* hwd    = hs + HW_D;
    __half* h16    = hs + H_H16;
    __half* qkv16  = hs + H_QKV16;
    __half* q16    = hs + H_Q16;
    __half* k16    = hs + H_K16;
    __half* p16    = hs + H_P16;
    __half* at16   = hs + H_ATTN16;
    __half* g16    = hs + H_G16;

    cudaFuncSetAttribute(casgemm_tn<1, 1>, cudaFuncAttributeMaxDynamicSharedMemorySize, CAS_SMEM_BYTES);
    cudaFuncSetAttribute(casgemm_tn<2, 0>, cudaFuncAttributeMaxDynamicSharedMemorySize, CAS_SMEM_BYTES);
    cudaFuncSetAttribute(casgemm_tn<0, 1>, cudaFuncAttributeMaxDynamicSharedMemorySize, CAS_SMEM_BYTES);
    cudaFuncSetAttribute(casgemm_tn<3, 1>, cudaFuncAttributeMaxDynamicSharedMemorySize, CAS_SMEM_BYTES);
    cudaFuncSetAttribute(hpv_cas,          cudaFuncAttributeMaxDynamicSharedMemorySize, PV_SMEM_BYTES);

    // 0. all weights fp32 -> fp16 in ONE launch (contiguous dst)
    f2h_all<<<8192, 256>>>(wq, wk, wv, wo, wg, wu, wd, hwqkv);
    bias_concat_kernel<<<12, 256>>>(bq, bk, bv, biasc);

    // 1. h16 = rmsnorm(x, ln1)
    rmsnorm_h_kernel<<<T_TOK, 256>>>(x, ln1, h16);

    // 2. fused QKV projection (+bias) -> fp16 qkv16
    casgemm_tn<1, 1><<<dim3(NQKV / 128, T_TOK / 128), 256, CAS_SMEM_BYTES>>>(
        h16, HIDN, hwqkv, HIDN, qkv16, NQKV, HIDN, biasc, nullptr, nullptr);

    // 3-4. per-head RMS + RoPE -> q16 (pre-scaled) / k16 ; V stays in qkv16
    head_rms_rope_h_kernel<<<dim3(T_TOK, NH),  HD>>>(qkv16, NQKV, 0,    qw, cosv, sinv, q16, HIDN, SCALE);
    head_rms_rope_h_kernel<<<dim3(T_TOK, NKV), HD>>>(qkv16, NQKV, HIDN, kw, cosv, sinv, k16, KVW, 1.0f);

    // 5. scores -> fp16 p16 (GQA K-reuse, lower triangle, analytic mask)
    hscores_g4<<<dim3(SEQ / 128, SEQ / 128, BATCH * NKV), 256>>>(q16, k16, p16);

    // 6. softmax in place (warp-per-row)
    softmax_kernel<<<BATCH * NH * SEQ / 8, 256>>>(p16);

    // 7. attn16 = P @ V (cp.async, heavy-first; V in-place in qkv16)
    hpv_cas<<<dim3(1, SEQ / 128, BATCH * NH), 256, PV_SMEM_BYTES>>>(
        p16, qkv16 + HIDN + KVW, NQKV, at16);

    // 8. x2 = x + attn @ wo^T
    casgemm_tn<2, 0><<<dim3(HIDN / 128, T_TOK / 128), 256, CAS_SMEM_BYTES>>>(
        at16, HIDN, hwo, HIDN, x2, HIDN, HIDN, nullptr, x, nullptr);

    // 9. h16 = rmsnorm(x2, ln2)
    rmsnorm_h_kernel<<<T_TOK, 256>>>(x2, ln2, h16);

    // 10. gate -> g16 (fp16)
    casgemm_tn<0, 1><<<dim3(FF / 128, T_TOK / 128), 256, CAS_SMEM_BYTES>>>(
        h16, HIDN, hwg, HIDN, g16, FF, HIDN, nullptr, nullptr, nullptr);

    // 11. up + fused silu: g16 = silu(g16) * up (in place)
    casgemm_tn<3, 1><<<dim3(FF / 128, T_TOK / 128), 256, CAS_SMEM_BYTES>>>(
        h16, HIDN, hwu, HIDN, g16, FF, HIDN, nullptr, nullptr, g16);

    // 12. out = x2 + g16 @ wd^T
    casgemm_tn<2, 0><<<dim3(HIDN / 128, T_TOK / 128), 256, CAS_SMEM_BYTES>>>(
        g16, FF, hwd, FF, out, HIDN, FF, nullptr, x2, nullptr);
}